// round 15
// baseline (speedup 1.0000x reference)
#include <cuda_runtime.h>
#include <math.h>
#include <stdint.h>

#define B_   4
#define T_   2048
#define HID_ 2048
#define NH_  16
#define HD_  128

// ---------------- scratch ---------------------------------------------------
__device__ __align__(128) float g_q   [(size_t)B_ * NH_ * T_ * HD_];  // tf32, scaled by 1/sqrt(HD)*log2e
__device__ __align__(128) float g_k   [(size_t)B_ * NH_ * T_ * HD_];  // tf32
__device__ __align__(128) float g_v   [(size_t)B_ * NH_ * T_ * HD_];  // [B,NH,HD,T] tf32 (transposed)
__device__ __align__(128) float g_attn[(size_t)B_ * T_ * HID_];       // v-slice [B,T,HID], then attn
__device__ __align__(128) float g_wqkv[(size_t)3 * HID_ * HID_];      // w_qkv, tf32-rounded
__device__ __align__(128) float g_wprj[(size_t)HID_ * HID_];          // w_proj, tf32-rounded

// ---------------- PTX helpers ----------------------------------------------
__device__ __forceinline__ uint32_t smem_u32(const void* p) {
    return (uint32_t)__cvta_generic_to_shared(p);
}
__device__ __forceinline__ void cp16(uint32_t s, const void* g) {
    asm volatile("cp.async.cg.shared.global [%0],[%1],16;\n" :: "r"(s), "l"(g));
}
__device__ __forceinline__ void cp_commit() { asm volatile("cp.async.commit_group;\n"); }
template<int N> __device__ __forceinline__ void cp_wait() {
    asm volatile("cp.async.wait_group %0;\n" :: "n"(N));
}
__device__ __forceinline__ void ldsm4(uint32_t* r, uint32_t a) {
    asm volatile("ldmatrix.sync.aligned.m8n8.x4.shared.b16 {%0,%1,%2,%3},[%4];\n"
                 : "=r"(r[0]), "=r"(r[1]), "=r"(r[2]), "=r"(r[3]) : "r"(a));
}
__device__ __forceinline__ void mma8(float* c, const uint32_t* a, uint32_t b0, uint32_t b1) {
    asm volatile("mma.sync.aligned.m16n8k8.row.col.f32.tf32.tf32.f32 "
                 "{%0,%1,%2,%3},{%4,%5,%6,%7},{%8,%9},{%0,%1,%2,%3};\n"
                 : "+f"(c[0]), "+f"(c[1]), "+f"(c[2]), "+f"(c[3])
                 : "r"(a[0]), "r"(a[1]), "r"(a[2]), "r"(a[3]), "r"(b0), "r"(b1));
}
__device__ __forceinline__ uint32_t f2tfu(float x) {
    uint32_t r; asm("cvt.rna.tf32.f32 %0,%1;\n" : "=r"(r) : "f"(x)); return r;
}
__device__ __forceinline__ float f2tf(float x) { return __uint_as_float(f2tfu(x)); }
__device__ __forceinline__ float fast_ex2(float x) {
    float r; asm("ex2.approx.ftz.f32 %0,%1;\n" : "=f"(r) : "f"(x)); return r;
}

// ---------------- tf32 GEMM v7 (NT): C[M,N]=A[M,K]@B[N,K]^T -----------------
// Tile 128x128, 256 threads (8 warps: 4M x 2N), warp tile 32x64, BK=32,
// 3-stage cp.async pipeline, 2 blocks/SM.
// A may be RAW fp32: A-fragments are tf32-RNA-rounded in-register post-ldsm
// (identity if already rounded). B must be pre-rounded.
#define GS 36   // smem row stride (floats)
#define SSTG (2*128*GS)

__global__ void __launch_bounds__(256, 2)
gemm_tf32_nt(const float* __restrict__ A, const float* __restrict__ Bw,
             const float* __restrict__ bias, float* __restrict__ C,
             int M, int N, int K, int mode,
             float* __restrict__ Qout, float* __restrict__ Kout,
             const float* __restrict__ cosb, const float* __restrict__ sinb)
{
    extern __shared__ __align__(16) float gsm[];   // 3 stages

    const int tid = threadIdx.x, l = tid & 31, w = tid >> 5;
    const int wm = w & 3, wn = w >> 2;
    const float* Ag = A  + (size_t)blockIdx.y * 128 * K;
    const float* Bg = Bw + (size_t)blockIdx.x * 128 * K;
    const uint32_t sbase = smem_u32(gsm);

    float acc[2][8][4];
#pragma unroll
    for (int i = 0; i < 2; ++i)
#pragma unroll
        for (int j = 0; j < 8; ++j)
#pragma unroll
            for (int k = 0; k < 4; ++k) acc[i][j][k] = 0.f;

    const int aOff = (wm*32 + (l & 7) + ((l >> 3) & 1) * 8) * GS + ((l >> 3) >> 1) * 4;
    const int bOff = (wn*64 + (l & 7) + ((l >> 4) & 1) * 8) * GS + ((l >> 3) & 1) * 4;

    const int lrA = tid >> 3, lcA = (tid & 7) * 4;
    auto load = [&](int kt, int st) {
        const float* Ak = Ag + (size_t)kt * 32;
        const float* Bk = Bg + (size_t)kt * 32;
        const uint32_t oA = sbase + st * SSTG * 4;
        const uint32_t oB = oA + 128 * GS * 4;
#pragma unroll
        for (int p = 0; p < 4; ++p) {
            int r = lrA + p * 32;
            cp16(oA + (r*GS + lcA) * 4, Ak + (size_t)r * K + lcA);
            cp16(oB + (r*GS + lcA) * 4, Bk + (size_t)r * K + lcA);
        }
        cp_commit();
    };

    load(0, 0);
    load(1, 1);

    const int nkt = K >> 5;
    for (int kt = 0; kt < nkt; ++kt) {
        const int st = kt % 3;
        if (kt + 1 < nkt) cp_wait<1>(); else cp_wait<0>();
        __syncthreads();
        if (kt + 2 < nkt) load(kt + 2, (kt + 2) % 3);

        const uint32_t aB = sbase + st * SSTG * 4;
        const uint32_t bB = aB + 128 * GS * 4;
#pragma unroll
        for (int ks = 0; ks < 4; ++ks) {
            const int k8 = ks * 8;
            uint32_t a[2][4], bf[8][2];
#pragma unroll
            for (int mi = 0; mi < 2; ++mi) {
                ldsm4(a[mi], aB + (aOff + mi*16*GS + k8) * 4);
#pragma unroll
                for (int q = 0; q < 4; ++q)
                    a[mi][q] = f2tfu(__uint_as_float(a[mi][q]));
            }
#pragma unroll
            for (int j = 0; j < 4; ++j) {
                uint32_t t[4];
                ldsm4(t, bB + (bOff + j*16*GS + k8) * 4);
                bf[2*j][0] = t[0]; bf[2*j][1] = t[1];
                bf[2*j+1][0] = t[2]; bf[2*j+1][1] = t[3];
            }
#pragma unroll
            for (int mi = 0; mi < 2; ++mi)
#pragma unroll
                for (int ni = 0; ni < 8; ++ni)
                    mma8(acc[mi][ni], a[mi], bf[ni][0], bf[ni][1]);
        }
    }

    const int rB = blockIdx.y * 128 + wm * 32 + (l >> 2);
    const int cB = blockIdx.x * 128 + wn * 64 + (l & 3) * 2;

    if (mode == 0) {
#pragma unroll
        for (int ni = 0; ni < 8; ++ni) {
            const int c = cB + ni * 8;
            float b0 = bias[c], b1 = bias[c + 1];
#pragma unroll
            for (int mi = 0; mi < 2; ++mi) {
                *(float2*)(C + (size_t)(rB + mi*16    ) * N + c) =
                    make_float2(acc[mi][ni][0] + b0, acc[mi][ni][1] + b1);
                *(float2*)(C + (size_t)(rB + mi*16 + 8) * N + c) =
                    make_float2(acc[mi][ni][2] + b0, acc[mi][ni][3] + b1);
            }
        }
    } else {
        const int sel = cB >> 11;
        const float QS = 0.088388347648318447f * 1.4426950408889634f;
#pragma unroll
        for (int ni = 0; ni < 8; ++ni) {
            const int c = cB + ni * 8;
            const int hd = c & 127, d2 = hd >> 1;
            const int head = (c & 2047) >> 7;
#pragma unroll
            for (int mi = 0; mi < 2; ++mi) {
#pragma unroll
                for (int hh = 0; hh < 2; ++hh) {
                    const int row = rB + mi*16 + hh*8;
                    const int t = row & 2047, bb = row >> 11;
                    const float ex = acc[mi][ni][hh*2], od = acc[mi][ni][hh*2+1];
                    if (sel == 2) {
                        *(float2*)(C + (size_t)row * 2048 + (c & 2047)) =
                            make_float2(ex, od);
                    } else {
                        const float cs = cosb[t*64 + d2], sn = sinb[t*64 + d2];
                        float rx = ex*cs - od*sn, ry = ex*sn + od*cs;
                        float* dst;
                        if (sel == 0) { rx *= QS; ry *= QS; dst = Qout; }
                        else          { dst = Kout; }
                        *(float2*)(dst + (((size_t)(bb*NH_ + head)) * T_ + t) * HD_ + hd) =
                            make_float2(f2tf(rx), f2tf(ry));
                    }
                }
            }
        }
    }
}

// ---------------- tf32-RNA rounding pass (two buffers, one launch) ----------
__global__ void __launch_bounds__(256)
cvt_tf32_dual_kernel(const float* __restrict__ in0, float* __restrict__ out0,
                     unsigned nb0,   // blocks for buffer 0
                     const float* __restrict__ in1, float* __restrict__ out1)
{
    const float* in;
    float* out;
    size_t base;
    if (blockIdx.x < nb0) { in = in0; out = out0; base = (size_t)blockIdx.x; }
    else                  { in = in1; out = out1; base = (size_t)(blockIdx.x - nb0); }
    size_t i = (base * 256 + threadIdx.x) * 4;
    float4 v = *(const float4*)(in + i);
    v.x = f2tf(v.x); v.y = f2tf(v.y); v.z = f2tf(v.z); v.w = f2tf(v.w);
    *(float4*)(out + i) = v;
}

// ---------------- V transpose: vsl [B,T,HID] -> [B,NH,HD,T] (tf32) ----------
__global__ void __launch_bounds__(256)
vtrans_kernel(const float* __restrict__ vsl, float* __restrict__ Vt)
{
    __shared__ float tile[32][33];
    const int t0 = blockIdx.x * 32, d0 = blockIdx.y * 32, bh = blockIdx.z;
    const int b = bh >> 4, h = bh & 15;
    const int tx = threadIdx.x & 31, ty = threadIdx.x >> 5;
#pragma unroll
    for (int p = 0; p < 4; ++p) {
        int tt = ty + p * 8;
        tile[tt][tx] = vsl[(size_t)(b * T_ + t0 + tt) * HID_ + h * HD_ + d0 + tx];
    }
    __syncthreads();
#pragma unroll
    for (int p = 0; p < 4; ++p) {
        int dd = ty + p * 8;
        Vt[((size_t)bh * HD_ + d0 + dd) * T_ + t0 + tx] = f2tf(tile[tx][dd]);
    }
}

// ---------------- Flash attention (champion geometry, fast ex2) -------------
__global__ void __launch_bounds__(256, 1)
flash_tf32_kernel(const float* __restrict__ Q, const float* __restrict__ K,
                  const float* __restrict__ V, float* __restrict__ O)
{
    extern __shared__ __align__(16) float sm[];
    float* Qs = sm;                       // 128*132
    float* Ks = Qs + 128 * 132;           // 2*64*132
    float* Vt = Ks + 2 * 64 * 132;        // 128*68
    float* Ps = Vt + 128 * 68;            // 128*68

    const int tid = threadIdx.x, l = tid & 31, w = tid >> 5;
    const int bm = blockIdx.x, h = blockIdx.y, b = blockIdx.z;
    const float* Qg = Q + (((size_t)b * NH_ + h) * T_ + (size_t)bm * 128) * HD_;
    const float* Kg = K + ((size_t)b * NH_ + h) * T_ * HD_;
    const float* Vg = V + ((size_t)b * NH_ + h) * (size_t)HD_ * T_;
    const uint32_t sQ = smem_u32(Qs), sK = smem_u32(Ks), sV = smem_u32(Vt), sP = smem_u32(Ps);

#pragma unroll
    for (int p = 0; p < 16; ++p) {
        int ci = tid + p * 256, r = ci >> 5, c = (ci & 31) * 4;
        cp16(sQ + (r * 132 + c) * 4, Qg + (size_t)r * HD_ + c);
    }
#pragma unroll
    for (int p = 0; p < 8; ++p) {
        int ci = tid + p * 256, r = ci >> 5, c = (ci & 31) * 4;
        cp16(sK + (r * 132 + c) * 4, Kg + (size_t)r * HD_ + c);
    }
    cp_commit();

    float o[16][4];
#pragma unroll
    for (int i = 0; i < 16; ++i)
#pragma unroll
        for (int j = 0; j < 4; ++j) o[i][j] = 0.f;
    float mA = -1e30f, mB = -1e30f, lA = 0.f, lB = 0.f;

    const int aOff  = (w*16 + (l & 7) + ((l >> 3) & 1) * 8) * 132 + ((l >> 3) >> 1) * 4;
    const int bOffK = ((l & 7) + ((l >> 4) & 1) * 8) * 132 + ((l >> 3) & 1) * 4;
    const int pOff  = (w*16 + (l & 7) + ((l >> 3) & 1) * 8) * 68 + ((l >> 3) >> 1) * 4;
    const int vOff  = ((l & 7) + ((l >> 4) & 1) * 8) * 68 + ((l >> 3) & 1) * 4;

    const int NIT = T_ / 64;
    for (int it = 0; it < NIT; ++it) {
        __syncthreads();
#pragma unroll
        for (int p = 0; p < 8; ++p) {
            int ci = tid + p * 256, r = ci >> 4, c = (ci & 15) * 4;
            cp16(sV + (r * 68 + c) * 4, Vg + (size_t)r * T_ + (size_t)it * 64 + c);
        }
        cp_commit();
        cp_wait<1>();
        __syncthreads();

        if (it + 1 < NIT) {
            const float* Kn = Kg + (size_t)(it + 1) * 64 * HD_;
            const int o2 = ((it + 1) & 1) * 64 * 132;
#pragma unroll
            for (int p = 0; p < 8; ++p) {
                int ci = tid + p * 256, r = ci >> 5, c = (ci & 31) * 4;
                cp16(sK + (o2 + r * 132 + c) * 4, Kn + (size_t)r * HD_ + c);
            }
            cp_commit();
        }

        const uint32_t kB = sK + (it & 1) * 64 * 132 * 4;
        float s[8][4];
#pragma unroll
        for (int i = 0; i < 8; ++i)
#pragma unroll
            for (int j = 0; j < 4; ++j) s[i][j] = 0.f;
#pragma unroll
        for (int ks = 0; ks < 16; ++ks) {
            const int k8 = ks * 8;
            uint32_t a[4];
            ldsm4(a, sQ + (aOff + k8) * 4);
#pragma unroll
            for (int j = 0; j < 4; ++j) {
                uint32_t t[4];
                ldsm4(t, kB + (bOffK + j * 16 * 132 + k8) * 4);
                mma8(s[2*j],   a, t[0], t[1]);
                mma8(s[2*j+1], a, t[2], t[3]);
            }
        }

        float mxA = -1e30f, mxB = -1e30f;
#pragma unroll
        for (int j = 0; j < 8; ++j) {
            mxA = fmaxf(mxA, fmaxf(s[j][0], s[j][1]));
            mxB = fmaxf(mxB, fmaxf(s[j][2], s[j][3]));
        }
        mxA = fmaxf(mxA, __shfl_xor_sync(0xffffffffu, mxA, 1));
        mxA = fmaxf(mxA, __shfl_xor_sync(0xffffffffu, mxA, 2));
        mxB = fmaxf(mxB, __shfl_xor_sync(0xffffffffu, mxB, 1));
        mxB = fmaxf(mxB, __shfl_xor_sync(0xffffffffu, mxB, 2));
        const float mnA = fmaxf(mA, mxA), mnB = fmaxf(mB, mxB);
        const float cA = fast_ex2(mA - mnA), cB = fast_ex2(mB - mnB);
        mA = mnA; mB = mnB;
        float sA_ = 0.f, sB_ = 0.f;
#pragma unroll
        for (int j = 0; j < 8; ++j) {
            s[j][0] = fast_ex2(s[j][0] - mnA);
            s[j][1] = fast_ex2(s[j][1] - mnA);
            s[j][2] = fast_ex2(s[j][2] - mnB);
            s[j][3] = fast_ex2(s[j][3] - mnB);
            sA_ += s[j][0] + s[j][1];
            sB_ += s[j][2] + s[j][3];
        }
        sA_ += __shfl_xor_sync(0xffffffffu, sA_, 1);
        sA_ += __shfl_xor_sync(0xffffffffu, sA_, 2);
        sB_ += __shfl_xor_sync(0xffffffffu, sB_, 1);
        sB_ += __shfl_xor_sync(0xffffffffu, sB_, 2);
        lA = lA * cA + sA_;
        lB = lB * cB + sB_;
#pragma unroll
        for (int t = 0; t < 16; ++t) {
            o[t][0] *= cA; o[t][1] *= cA; o[t][2] *= cB; o[t][3] *= cB;
        }

        {
            const int pr = w * 16 + (l >> 2);
            float* P0 = Ps + pr * 68 + (l & 3) * 2;
            float* P1 = Ps + (pr + 8) * 68 + (l & 3) * 2;
#pragma unroll
            for (int j = 0; j < 8; ++j) {
                *(float2*)(P0 + j * 8) = make_float2(s[j][0], s[j][1]);
                *(float2*)(P1 + j * 8) = make_float2(s[j][2], s[j][3]);
            }
        }
        __syncwarp();
        if (it + 1 < NIT) cp_wait<1>(); else cp_wait<0>();
        __syncthreads();

#pragma unroll
        for (int kv = 0; kv < 8; ++kv) {
            uint32_t a[4];
            ldsm4(a, sP + (pOff + kv * 8) * 4);
#pragma unroll
            for (int j = 0; j < 8; ++j) {
                uint32_t t[4];
                ldsm4(t, sV + (vOff + j * 16 * 68 + kv * 8) * 4);
                mma8(o[2*j],   a, t[0], t[1]);
                mma8(o[2*j+1], a, t[2], t[3]);
            }
        }
    }

    const float iA = 1.f / lA, iB = 1.f / lB;
    const int row = bm * 128 + w * 16 + (l >> 2);
    float* O0 = O + ((size_t)b * T_ + row) * HID_ + h * HD_ + (l & 3) * 2;
    float* O1 = O + ((size_t)b * T_ + row + 8) * HID_ + h * HD_ + (l & 3) * 2;
#pragma unroll
    for (int j = 0; j < 16; ++j) {
        *(float2*)(O0 + j * 8) = make_float2(f2tf(o[j][0] * iA), f2tf(o[j][1] * iA));
        *(float2*)(O1 + j * 8) = make_float2(f2tf(o[j][2] * iB), f2tf(o[j][3] * iB));
    }
}

// ---------------- launch ----------------------------------------------------
extern "C" void kernel_launch(void* const* d_in, const int* in_sizes, int n_in,
                              void* d_out, int out_size)
{
    const float* x      = (const float*)d_in[0];
    const float* w_qkv  = (const float*)d_in[1];
    const float* w_proj = (const float*)d_in[2];
    const float* b_proj = (const float*)d_in[3];
    const float* cosb   = (const float*)d_in[4];
    const float* sinb   = (const float*)d_in[5];
    float* out = (float*)d_out;

    float *q, *k, *v, *attn, *wqkv, *wprj;
    cudaGetSymbolAddress((void**)&q,    g_q);
    cudaGetSymbolAddress((void**)&k,    g_k);
    cudaGetSymbolAddress((void**)&v,    g_v);
    cudaGetSymbolAddress((void**)&attn, g_attn);
    cudaGetSymbolAddress((void**)&wqkv, g_wqkv);
    cudaGetSymbolAddress((void**)&wprj, g_wprj);

    const int SMEM_GEMM = 3 * SSTG * 4;                                 // 110592
    const int SMEM_ATT  = (128*132 + 2*64*132 + 128*68 + 128*68) * 4;   // 204800
    cudaFuncSetAttribute(gemm_tf32_nt,
                         cudaFuncAttributeMaxDynamicSharedMemorySize, SMEM_GEMM);
    cudaFuncSetAttribute(flash_tf32_kernel,
                         cudaFuncAttributeMaxDynamicSharedMemorySize, SMEM_ATT);

    const int M = B_ * T_;   // 8192

    // 0) tf32-RNA rounding of BOTH weight buffers in ONE launch.
    //    x stays raw: the QKV GEMM rounds its A-fragments in-register.
    const unsigned nb0 = (unsigned)((size_t)3 * HID_ * HID_ / 1024);   // wqkv blocks
    const unsigned nb1 = (unsigned)((size_t)HID_ * HID_ / 1024);       // wprj blocks
    cvt_tf32_dual_kernel<<<nb0 + nb1, 256>>>(w_qkv, wqkv, nb0, w_proj, wprj);

    // 1) QKV projection + fused RoPE/split. V-slice lands in attn buffer.
    dim3 g1(3 * HID_ / 128, M / 128);
    gemm_tf32_nt<<<g1, 256, SMEM_GEMM>>>(x, wqkv, nullptr, attn,
                                         M, 3 * HID_, HID_, 1,
                                         q, k, cosb, sinb);

    // 2) V transpose -> [B,NH,HD,T]
    dim3 gv(T_ / 32, HD_ / 32, B_ * NH_);
    vtrans_kernel<<<gv, 256>>>(attn, v);

    // 3) Flash attention (overwrites attn)
    dim3 ga(T_ / 128, NH_, B_);
    flash_tf32_kernel<<<ga, 256, SMEM_ATT>>>(q, k, v, attn);

    // 4) Output projection + bias (A=attn already tf32; in-register cvt is identity)
    dim3 g2(HID_ / 128, M / 128);
    gemm_tf32_nt<<<g2, 256, SMEM_GEMM>>>(attn, wprj, b_proj, out,
                                         M, HID_, HID_, 0,
                                         nullptr, nullptr, nullptr, nullptr);
}

// round 16
// speedup vs baseline: 1.0301x; 1.0301x over previous
#include <cuda_runtime.h>
#include <math.h>
#include <stdint.h>

#define B_   4
#define T_   2048
#define HID_ 2048
#define NH_  16
#define HD_  128

// ---------------- scratch ---------------------------------------------------
__device__ __align__(128) float g_q   [(size_t)B_ * NH_ * T_ * HD_];  // tf32, scaled by 1/sqrt(HD)*log2e
__device__ __align__(128) float g_k   [(size_t)B_ * NH_ * T_ * HD_];  // tf32
__device__ __align__(128) float g_v   [(size_t)B_ * NH_ * T_ * HD_];  // [B,NH,HD,T] tf32 (transposed)
__device__ __align__(128) float g_attn[(size_t)B_ * T_ * HID_];       // v-slice [B,T,HID], then attn
__device__ __align__(128) float g_xtf [(size_t)B_ * T_ * HID_];       // x, tf32-rounded
__device__ __align__(128) float g_wqkv[(size_t)3 * HID_ * HID_];      // w_qkv, tf32-rounded
__device__ __align__(128) float g_wprj[(size_t)HID_ * HID_];          // w_proj, tf32-rounded

// ---------------- PTX helpers ----------------------------------------------
__device__ __forceinline__ uint32_t smem_u32(const void* p) {
    return (uint32_t)__cvta_generic_to_shared(p);
}
__device__ __forceinline__ void cp16(uint32_t s, const void* g) {
    asm volatile("cp.async.cg.shared.global [%0],[%1],16;\n" :: "r"(s), "l"(g));
}
__device__ __forceinline__ void cp_commit() { asm volatile("cp.async.commit_group;\n"); }
template<int N> __device__ __forceinline__ void cp_wait() {
    asm volatile("cp.async.wait_group %0;\n" :: "n"(N));
}
__device__ __forceinline__ void ldsm4(uint32_t* r, uint32_t a) {
    asm volatile("ldmatrix.sync.aligned.m8n8.x4.shared.b16 {%0,%1,%2,%3},[%4];\n"
                 : "=r"(r[0]), "=r"(r[1]), "=r"(r[2]), "=r"(r[3]) : "r"(a));
}
__device__ __forceinline__ void mma8(float* c, const uint32_t* a, uint32_t b0, uint32_t b1) {
    asm volatile("mma.sync.aligned.m16n8k8.row.col.f32.tf32.tf32.f32 "
                 "{%0,%1,%2,%3},{%4,%5,%6,%7},{%8,%9},{%0,%1,%2,%3};\n"
                 : "+f"(c[0]), "+f"(c[1]), "+f"(c[2]), "+f"(c[3])
                 : "r"(a[0]), "r"(a[1]), "r"(a[2]), "r"(a[3]), "r"(b0), "r"(b1));
}
__device__ __forceinline__ uint32_t f2tfu(float x) {
    uint32_t r; asm("cvt.rna.tf32.f32 %0,%1;\n" : "=r"(r) : "f"(x)); return r;
}
__device__ __forceinline__ float f2tf(float x) { return __uint_as_float(f2tfu(x)); }
__device__ __forceinline__ float fast_ex2(float x) {
    float r; asm("ex2.approx.ftz.f32 %0,%1;\n" : "=f"(r) : "f"(x)); return r;
}

// ---------------- tf32 GEMM v6 (NT): C[M,N]=A[M,K]@B[N,K]^T -----------------
// Tile 128x128, 256 threads (8 warps: 4M x 2N), warp tile 32x64, BK=32,
// 3-stage cp.async pipeline, 2 blocks/SM. Operands pre-rounded to tf32.
#define GS 36   // smem row stride (floats)
#define SSTG (2*128*GS)

__global__ void __launch_bounds__(256, 2)
gemm_tf32_nt(const float* __restrict__ A, const float* __restrict__ Bw,
             const float* __restrict__ bias, float* __restrict__ C,
             int M, int N, int K, int mode,
             float* __restrict__ Qout, float* __restrict__ Kout,
             const float* __restrict__ cosb, const float* __restrict__ sinb)
{
    extern __shared__ __align__(16) float gsm[];   // 3 stages

    const int tid = threadIdx.x, l = tid & 31, w = tid >> 5;
    const int wm = w & 3, wn = w >> 2;
    const float* Ag = A  + (size_t)blockIdx.y * 128 * K;
    const float* Bg = Bw + (size_t)blockIdx.x * 128 * K;
    const uint32_t sbase = smem_u32(gsm);

    float acc[2][8][4];
#pragma unroll
    for (int i = 0; i < 2; ++i)
#pragma unroll
        for (int j = 0; j < 8; ++j)
#pragma unroll
            for (int k = 0; k < 4; ++k) acc[i][j][k] = 0.f;

    const int aOff = (wm*32 + (l & 7) + ((l >> 3) & 1) * 8) * GS + ((l >> 3) >> 1) * 4;
    const int bOff = (wn*64 + (l & 7) + ((l >> 4) & 1) * 8) * GS + ((l >> 3) & 1) * 4;

    const int lrA = tid >> 3, lcA = (tid & 7) * 4;
    auto load = [&](int kt, int st) {
        const float* Ak = Ag + (size_t)kt * 32;
        const float* Bk = Bg + (size_t)kt * 32;
        const uint32_t oA = sbase + st * SSTG * 4;
        const uint32_t oB = oA + 128 * GS * 4;
#pragma unroll
        for (int p = 0; p < 4; ++p) {
            int r = lrA + p * 32;
            cp16(oA + (r*GS + lcA) * 4, Ak + (size_t)r * K + lcA);
            cp16(oB + (r*GS + lcA) * 4, Bk + (size_t)r * K + lcA);
        }
        cp_commit();
    };

    load(0, 0);
    load(1, 1);

    const int nkt = K >> 5;
    for (int kt = 0; kt < nkt; ++kt) {
        const int st = kt % 3;
        if (kt + 1 < nkt) cp_wait<1>(); else cp_wait<0>();
        __syncthreads();
        if (kt + 2 < nkt) load(kt + 2, (kt + 2) % 3);

        const uint32_t aB = sbase + st * SSTG * 4;
        const uint32_t bB = aB + 128 * GS * 4;
#pragma unroll
        for (int ks = 0; ks < 4; ++ks) {
            const int k8 = ks * 8;
            uint32_t a[2][4], bf[8][2];
#pragma unroll
            for (int mi = 0; mi < 2; ++mi)
                ldsm4(a[mi], aB + (aOff + mi*16*GS + k8) * 4);
#pragma unroll
            for (int j = 0; j < 4; ++j) {
                uint32_t t[4];
                ldsm4(t, bB + (bOff + j*16*GS + k8) * 4);
                bf[2*j][0] = t[0]; bf[2*j][1] = t[1];
                bf[2*j+1][0] = t[2]; bf[2*j+1][1] = t[3];
            }
#pragma unroll
            for (int mi = 0; mi < 2; ++mi)
#pragma unroll
                for (int ni = 0; ni < 8; ++ni)
                    mma8(acc[mi][ni], a[mi], bf[ni][0], bf[ni][1]);
        }
    }

    const int rB = blockIdx.y * 128 + wm * 32 + (l >> 2);
    const int cB = blockIdx.x * 128 + wn * 64 + (l & 3) * 2;

    if (mode == 0) {
#pragma unroll
        for (int ni = 0; ni < 8; ++ni) {
            const int c = cB + ni * 8;
            float b0 = bias[c], b1 = bias[c + 1];
#pragma unroll
            for (int mi = 0; mi < 2; ++mi) {
                *(float2*)(C + (size_t)(rB + mi*16    ) * N + c) =
                    make_float2(acc[mi][ni][0] + b0, acc[mi][ni][1] + b1);
                *(float2*)(C + (size_t)(rB + mi*16 + 8) * N + c) =
                    make_float2(acc[mi][ni][2] + b0, acc[mi][ni][3] + b1);
            }
        }
    } else {
        const int sel = cB >> 11;
        const float QS = 0.088388347648318447f * 1.4426950408889634f;
#pragma unroll
        for (int ni = 0; ni < 8; ++ni) {
            const int c = cB + ni * 8;
            const int hd = c & 127, d2 = hd >> 1;
            const int head = (c & 2047) >> 7;
#pragma unroll
            for (int mi = 0; mi < 2; ++mi) {
#pragma unroll
                for (int hh = 0; hh < 2; ++hh) {
                    const int row = rB + mi*16 + hh*8;
                    const int t = row & 2047, bb = row >> 11;
                    const float ex = acc[mi][ni][hh*2], od = acc[mi][ni][hh*2+1];
                    if (sel == 2) {
                        *(float2*)(C + (size_t)row * 2048 + (c & 2047)) =
                            make_float2(ex, od);
                    } else {
                        const float cs = cosb[t*64 + d2], sn = sinb[t*64 + d2];
                        float rx = ex*cs - od*sn, ry = ex*sn + od*cs;
                        float* dst;
                        if (sel == 0) { rx *= QS; ry *= QS; dst = Qout; }
                        else          { dst = Kout; }
                        *(float2*)(dst + (((size_t)(bb*NH_ + head)) * T_ + t) * HD_ + hd) =
                            make_float2(f2tf(rx), f2tf(ry));
                    }
                }
            }
        }
    }
}

// ---------------- tf32-RNA rounding pass (three buffers, one launch) --------
__global__ void __launch_bounds__(256)
cvt_tf32_tri_kernel(const float* __restrict__ in0, float* __restrict__ out0, unsigned nb0,
                    const float* __restrict__ in1, float* __restrict__ out1, unsigned nb1,
                    const float* __restrict__ in2, float* __restrict__ out2)
{
    const float* in;
    float* out;
    size_t base;
    if (blockIdx.x < nb0)             { in = in0; out = out0; base = blockIdx.x; }
    else if (blockIdx.x < nb0 + nb1)  { in = in1; out = out1; base = blockIdx.x - nb0; }
    else                              { in = in2; out = out2; base = blockIdx.x - nb0 - nb1; }
    size_t i = (base * 256 + threadIdx.x) * 4;
    float4 v = *(const float4*)(in + i);
    v.x = f2tf(v.x); v.y = f2tf(v.y); v.z = f2tf(v.z); v.w = f2tf(v.w);
    *(float4*)(out + i) = v;
}

// ---------------- V transpose: vsl [B,T,HID] -> [B,NH,HD,T] (tf32) ----------
__global__ void __launch_bounds__(256)
vtrans_kernel(const float* __restrict__ vsl, float* __restrict__ Vt)
{
    __shared__ float tile[32][33];
    const int t0 = blockIdx.x * 32, d0 = blockIdx.y * 32, bh = blockIdx.z;
    const int b = bh >> 4, h = bh & 15;
    const int tx = threadIdx.x & 31, ty = threadIdx.x >> 5;
#pragma unroll
    for (int p = 0; p < 4; ++p) {
        int tt = ty + p * 8;
        tile[tt][tx] = vsl[(size_t)(b * T_ + t0 + tt) * HID_ + h * HD_ + d0 + tx];
    }
    __syncthreads();
#pragma unroll
    for (int p = 0; p < 4; ++p) {
        int dd = ty + p * 8;
        Vt[((size_t)bh * HD_ + d0 + dd) * T_ + t0 + tx] = f2tf(tile[tx][dd]);
    }
}

// ---------------- Flash attention (champion geometry, fast ex2) -------------
__global__ void __launch_bounds__(256, 1)
flash_tf32_kernel(const float* __restrict__ Q, const float* __restrict__ K,
                  const float* __restrict__ V, float* __restrict__ O)
{
    extern __shared__ __align__(16) float sm[];
    float* Qs = sm;                       // 128*132
    float* Ks = Qs + 128 * 132;           // 2*64*132
    float* Vt = Ks + 2 * 64 * 132;        // 128*68
    float* Ps = Vt + 128 * 68;            // 128*68

    const int tid = threadIdx.x, l = tid & 31, w = tid >> 5;
    const int bm = blockIdx.x, h = blockIdx.y, b = blockIdx.z;
    const float* Qg = Q + (((size_t)b * NH_ + h) * T_ + (size_t)bm * 128) * HD_;
    const float* Kg = K + ((size_t)b * NH_ + h) * T_ * HD_;
    const float* Vg = V + ((size_t)b * NH_ + h) * (size_t)HD_ * T_;
    const uint32_t sQ = smem_u32(Qs), sK = smem_u32(Ks), sV = smem_u32(Vt), sP = smem_u32(Ps);

#pragma unroll
    for (int p = 0; p < 16; ++p) {
        int ci = tid + p * 256, r = ci >> 5, c = (ci & 31) * 4;
        cp16(sQ + (r * 132 + c) * 4, Qg + (size_t)r * HD_ + c);
    }
#pragma unroll
    for (int p = 0; p < 8; ++p) {
        int ci = tid + p * 256, r = ci >> 5, c = (ci & 31) * 4;
        cp16(sK + (r * 132 + c) * 4, Kg + (size_t)r * HD_ + c);
    }
    cp_commit();

    float o[16][4];
#pragma unroll
    for (int i = 0; i < 16; ++i)
#pragma unroll
        for (int j = 0; j < 4; ++j) o[i][j] = 0.f;
    float mA = -1e30f, mB = -1e30f, lA = 0.f, lB = 0.f;

    const int aOff  = (w*16 + (l & 7) + ((l >> 3) & 1) * 8) * 132 + ((l >> 3) >> 1) * 4;
    const int bOffK = ((l & 7) + ((l >> 4) & 1) * 8) * 132 + ((l >> 3) & 1) * 4;
    const int pOff  = (w*16 + (l & 7) + ((l >> 3) & 1) * 8) * 68 + ((l >> 3) >> 1) * 4;
    const int vOff  = ((l & 7) + ((l >> 4) & 1) * 8) * 68 + ((l >> 3) & 1) * 4;

    const int NIT = T_ / 64;
    for (int it = 0; it < NIT; ++it) {
        __syncthreads();
#pragma unroll
        for (int p = 0; p < 8; ++p) {
            int ci = tid + p * 256, r = ci >> 4, c = (ci & 15) * 4;
            cp16(sV + (r * 68 + c) * 4, Vg + (size_t)r * T_ + (size_t)it * 64 + c);
        }
        cp_commit();
        cp_wait<1>();
        __syncthreads();

        if (it + 1 < NIT) {
            const float* Kn = Kg + (size_t)(it + 1) * 64 * HD_;
            const int o2 = ((it + 1) & 1) * 64 * 132;
#pragma unroll
            for (int p = 0; p < 8; ++p) {
                int ci = tid + p * 256, r = ci >> 5, c = (ci & 31) * 4;
                cp16(sK + (o2 + r * 132 + c) * 4, Kn + (size_t)r * HD_ + c);
            }
            cp_commit();
        }

        const uint32_t kB = sK + (it & 1) * 64 * 132 * 4;
        float s[8][4];
#pragma unroll
        for (int i = 0; i < 8; ++i)
#pragma unroll
            for (int j = 0; j < 4; ++j) s[i][j] = 0.f;
#pragma unroll
        for (int ks = 0; ks < 16; ++ks) {
            const int k8 = ks * 8;
            uint32_t a[4];
            ldsm4(a, sQ + (aOff + k8) * 4);
#pragma unroll
            for (int j = 0; j < 4; ++j) {
                uint32_t t[4];
                ldsm4(t, kB + (bOffK + j * 16 * 132 + k8) * 4);
                mma8(s[2*j],   a, t[0], t[1]);
                mma8(s[2*j+1], a, t[2], t[3]);
            }
        }

        float mxA = -1e30f, mxB = -1e30f;
#pragma unroll
        for (int j = 0; j < 8; ++j) {
            mxA = fmaxf(mxA, fmaxf(s[j][0], s[j][1]));
            mxB = fmaxf(mxB, fmaxf(s[j][2], s[j][3]));
        }
        mxA = fmaxf(mxA, __shfl_xor_sync(0xffffffffu, mxA, 1));
        mxA = fmaxf(mxA, __shfl_xor_sync(0xffffffffu, mxA, 2));
        mxB = fmaxf(mxB, __shfl_xor_sync(0xffffffffu, mxB, 1));
        mxB = fmaxf(mxB, __shfl_xor_sync(0xffffffffu, mxB, 2));
        const float mnA = fmaxf(mA, mxA), mnB = fmaxf(mB, mxB);
        const float cA = fast_ex2(mA - mnA), cB = fast_ex2(mB - mnB);
        mA = mnA; mB = mnB;
        float sA_ = 0.f, sB_ = 0.f;
#pragma unroll
        for (int j = 0; j < 8; ++j) {
            s[j][0] = fast_ex2(s[j][0] - mnA);
            s[j][1] = fast_ex2(s[j][1] - mnA);
            s[j][2] = fast_ex2(s[j][2] - mnB);
            s[j][3] = fast_ex2(s[j][3] - mnB);
            sA_ += s[j][0] + s[j][1];
            sB_ += s[j][2] + s[j][3];
        }
        sA_ += __shfl_xor_sync(0xffffffffu, sA_, 1);
        sA_ += __shfl_xor_sync(0xffffffffu, sA_, 2);
        sB_ += __shfl_xor_sync(0xffffffffu, sB_, 1);
        sB_ += __shfl_xor_sync(0xffffffffu, sB_, 2);
        lA = lA * cA + sA_;
        lB = lB * cB + sB_;
#pragma unroll
        for (int t = 0; t < 16; ++t) {
            o[t][0] *= cA; o[t][1] *= cA; o[t][2] *= cB; o[t][3] *= cB;
        }

        {
            const int pr = w * 16 + (l >> 2);
            float* P0 = Ps + pr * 68 + (l & 3) * 2;
            float* P1 = Ps + (pr + 8) * 68 + (l & 3) * 2;
#pragma unroll
            for (int j = 0; j < 8; ++j) {
                *(float2*)(P0 + j * 8) = make_float2(s[j][0], s[j][1]);
                *(float2*)(P1 + j * 8) = make_float2(s[j][2], s[j][3]);
            }
        }
        __syncwarp();
        if (it + 1 < NIT) cp_wait<1>(); else cp_wait<0>();
        __syncthreads();

#pragma unroll
        for (int kv = 0; kv < 8; ++kv) {
            uint32_t a[4];
            ldsm4(a, sP + (pOff + kv * 8) * 4);
#pragma unroll
            for (int j = 0; j < 8; ++j) {
                uint32_t t[4];
                ldsm4(t, sV + (vOff + j * 16 * 68 + kv * 8) * 4);
                mma8(o[2*j],   a, t[0], t[1]);
                mma8(o[2*j+1], a, t[2], t[3]);
            }
        }
    }

    const float iA = 1.f / lA, iB = 1.f / lB;
    const int row = bm * 128 + w * 16 + (l >> 2);
    float* O0 = O + ((size_t)b * T_ + row) * HID_ + h * HD_ + (l & 3) * 2;
    float* O1 = O + ((size_t)b * T_ + row + 8) * HID_ + h * HD_ + (l & 3) * 2;
#pragma unroll
    for (int j = 0; j < 16; ++j) {
        *(float2*)(O0 + j * 8) = make_float2(f2tf(o[j][0] * iA), f2tf(o[j][1] * iA));
        *(float2*)(O1 + j * 8) = make_float2(f2tf(o[j][2] * iB), f2tf(o[j][3] * iB));
    }
}

// ---------------- launch ----------------------------------------------------
extern "C" void kernel_launch(void* const* d_in, const int* in_sizes, int n_in,
                              void* d_out, int out_size)
{
    const float* x      = (const float*)d_in[0];
    const float* w_qkv  = (const float*)d_in[1];
    const float* w_proj = (const float*)d_in[2];
    const float* b_proj = (const float*)d_in[3];
    const float* cosb   = (const float*)d_in[4];
    const float* sinb   = (const float*)d_in[5];
    float* out = (float*)d_out;

    float *q, *k, *v, *attn, *xtf, *wqkv, *wprj;
    cudaGetSymbolAddress((void**)&q,    g_q);
    cudaGetSymbolAddress((void**)&k,    g_k);
    cudaGetSymbolAddress((void**)&v,    g_v);
    cudaGetSymbolAddress((void**)&attn, g_attn);
    cudaGetSymbolAddress((void**)&xtf,  g_xtf);
    cudaGetSymbolAddress((void**)&wqkv, g_wqkv);
    cudaGetSymbolAddress((void**)&wprj, g_wprj);

    const int SMEM_GEMM = 3 * SSTG * 4;                                 // 110592
    const int SMEM_ATT  = (128*132 + 2*64*132 + 128*68 + 128*68) * 4;   // 204800
    cudaFuncSetAttribute(gemm_tf32_nt,
                         cudaFuncAttributeMaxDynamicSharedMemorySize, SMEM_GEMM);
    cudaFuncSetAttribute(flash_tf32_kernel,
                         cudaFuncAttributeMaxDynamicSharedMemorySize, SMEM_ATT);

    const int M = B_ * T_;   // 8192

    // 0) tf32-RNA rounding of x + both weights, ONE launch
    const unsigned nb0 = (unsigned)((size_t)M * HID_ / 1024);          // x blocks
    const unsigned nb1 = (unsigned)((size_t)3 * HID_ * HID_ / 1024);   // wqkv blocks
    const unsigned nb2 = (unsigned)((size_t)HID_ * HID_ / 1024);       // wprj blocks
    cvt_tf32_tri_kernel<<<nb0 + nb1 + nb2, 256>>>(x, xtf, nb0,
                                                  w_qkv, wqkv, nb1,
                                                  w_proj, wprj);

    // 1) QKV projection + fused RoPE/split. V-slice lands in attn buffer.
    dim3 g1(3 * HID_ / 128, M / 128);
    gemm_tf32_nt<<<g1, 256, SMEM_GEMM>>>(xtf, wqkv, nullptr, attn,
                                         M, 3 * HID_, HID_, 1,
                                         q, k, cosb, sinb);

    // 2) V transpose -> [B,NH,HD,T]
    dim3 gv(T_ / 32, HD_ / 32, B_ * NH_);
    vtrans_kernel<<<gv, 256>>>(attn, v);

    // 3) Flash attention (overwrites attn)
    dim3 ga(T_ / 128, NH_, B_);
    flash_tf32_kernel<<<ga, 256, SMEM_ATT>>>(q, k, v, attn);

    // 4) Output projection + bias (attn already tf32-exact)
    dim3 g2(HID_ / 128, M / 128);
    gemm_tf32_nt<<<g2, 256, SMEM_GEMM>>>(attn, wprj, b_proj, out,
                                         M, HID_, HID_, 0,
                                         nullptr, nullptr, nullptr, nullptr);
}